// round 1
// baseline (speedup 1.0000x reference)
#include <cuda_runtime.h>

#define KS 48
#define NT 256

// shared memory layout (floats)
constexpr int SX_STRIDE  = 49;   // X[c][h]
constexpr int QKV_STRIDE = 49;   // QKV[o][h]
constexpr int REL_STRIDE = 97;   // rel[c][d], d in [0,95)
constexpr int MAT_STRIDE = 52;   // qr/kr/sim [48][52], float4-friendly
constexpr int OUT_STRIDE = 65;   // out[i][p]

constexpr int OFF_X   = 0;
constexpr int OFF_W   = OFF_X   + 64 * SX_STRIDE;     // 3136
constexpr int OFF_QKV = OFF_W   + 128 * 64;           // +8192
constexpr int OFF_REL = OFF_QKV + 128 * QKV_STRIDE;   // +6272
constexpr int OFF_QR  = OFF_REL + 16 * REL_STRIDE;    // +1552
constexpr int OFF_KR  = OFF_QR  + 2 * 48 * MAT_STRIDE;
constexpr int OFF_SIM = OFF_KR  + 2 * 48 * MAT_STRIDE;
constexpr int OFF_OUT = OFF_SIM + 2 * 48 * MAT_STRIDE;
constexpr int OFF_PAR = OFF_OUT + 48 * OUT_STRIDE;
constexpr int SMEM_FLOATS = OFF_PAR + 6 * 48;
constexpr int SMEM_BYTES  = SMEM_FLOATS * 4;          // 150144 B

__global__ void __launch_bounds__(NT, 1) axial_kernel(
    const float* __restrict__ x,      const float* __restrict__ w_qkv,
    const float* __restrict__ relv,
    const float* __restrict__ g_qkv,  const float* __restrict__ b_qkv,
    const float* __restrict__ g_sim,  const float* __restrict__ b_sim,
    const float* __restrict__ g_out,  const float* __restrict__ b_out,
    float* __restrict__ out)
{
    extern __shared__ float sm[];
    float* sX   = sm + OFF_X;
    float* sW   = sm + OFF_W;
    float* sQKV = sm + OFF_QKV;
    float* sRel = sm + OFF_REL;
    float* sOut = sm + OFF_OUT;
    float* sGQ  = sm + OFF_PAR;
    float* sBQ  = sGQ + 48; float* sGS = sBQ + 48; float* sBS = sGS + 48;
    float* sGO  = sBS + 48; float* sBO = sGO + 48;

    const int tid = threadIdx.x;
    const int blk = blockIdx.x;
    const int wi = blk / KS, li = blk % KS;

    // ---- load X (as [c][h]), W, relative, BN params ----
    for (int idx = tid; idx < KS * 64; idx += NT) {
        const int h = idx >> 6, c = idx & 63;
        sX[c * SX_STRIDE + h] = x[((h * KS + wi) * KS + li) * 64 + c];
    }
    for (int idx = tid; idx < 128 * 64; idx += NT) sW[idx] = w_qkv[idx];
    for (int idx = tid; idx < 16 * 95; idx += NT)
        sRel[(idx / 95) * REL_STRIDE + (idx % 95)] = relv[idx];
    if (tid < KS) {
        const float inv = rsqrtf(1.001f);
        sGQ[tid] = g_qkv[tid] * inv; sBQ[tid] = b_qkv[tid];
        sGS[tid] = g_sim[tid] * inv; sBS[tid] = 3.0f * b_sim[tid];
        sGO[tid] = g_out[tid] * inv; sBO[tid] = 2.0f * b_out[tid];
    }
    __syncthreads();

    // ---- QKV = BN(W @ X) : 128x48, tiles of 4o x 2h ----
    for (int slot = tid; slot < 32 * 24; slot += NT) {
        const int o0 = (slot / 24) * 4;
        const int h0 = (slot % 24) * 2;
        float a[4][2] = {};
        #pragma unroll 8
        for (int c = 0; c < 64; ++c) {
            const float x0 = sX[c * SX_STRIDE + h0];
            const float x1 = sX[c * SX_STRIDE + h0 + 1];
            #pragma unroll
            for (int q = 0; q < 4; ++q) {
                const float wv = sW[(o0 + q) * 64 + c];
                a[q][0] += wv * x0;
                a[q][1] += wv * x1;
            }
        }
        const float g0 = sGQ[h0], g1 = sGQ[h0 + 1];
        const float c0 = sBQ[h0], c1 = sBQ[h0 + 1];
        #pragma unroll
        for (int q = 0; q < 4; ++q) {
            sQKV[(o0 + q) * QKV_STRIDE + h0]     = a[q][0] * g0 + c0;
            sQKV[(o0 + q) * QKV_STRIDE + h0 + 1] = a[q][1] * g1 + c1;
        }
    }
    __syncthreads();

    // ---- per-group pipeline; two groups in parallel (128 threads each) ----
    const int sub = tid >> 7;      // 0 or 1
    const int t0  = tid & 127;
    float* sQR  = sm + OFF_QR  + sub * (48 * MAT_STRIDE);
    float* sKR  = sm + OFF_KR  + sub * (48 * MAT_STRIDE);
    float* sSim = sm + OFF_SIM + sub * (48 * MAT_STRIDE);

    for (int gp = 0; gp < 8; gp += 2) {
        const int g = gp + sub;
        const float* Q  = sQKV + (16 * g)     * QKV_STRIDE;
        const float* Km = sQKV + (16 * g + 4) * QKV_STRIDE;
        const float* V  = sQKV + (16 * g + 8) * QKV_STRIDE;

        // qr[m][i] = sum_c q[c,m] * rel[c, m-i+47]
        // kr[m][j] = sum_c k[c,j] * rel[4+c, j-m+47]   (post-swap layout)
        for (int s = t0; s < KS * KS; s += 128) {
            const int m = s / KS, i = s % KS;
            float aq = 0.f, ak = 0.f;
            #pragma unroll
            for (int c = 0; c < 4; ++c) {
                aq += Q[c * QKV_STRIDE + m]  * sRel[c * REL_STRIDE + (m - i + 47)];
                ak += Km[c * QKV_STRIDE + i] * sRel[(4 + c) * REL_STRIDE + (i - m + 47)];
            }
            sQR[m * MAT_STRIDE + i] = aq;
            sKR[m * MAT_STRIDE + i] = ak;
        }
        __syncthreads();

        // qk[i,j] = sum_m qr[m,i]*kr[m,j]; sim_in = (qk+qr+kr)*gs[j] + 3*bs[j]
        for (int ts = t0; ts < 144; ts += 128) {
            const int i0 = (ts / 12) * 4, j0 = (ts % 12) * 4;
            float acc[4][4] = {};
            #pragma unroll 2
            for (int m = 0; m < KS; ++m) {
                const float4 qv = *reinterpret_cast<const float4*>(&sQR[m * MAT_STRIDE + i0]);
                const float4 kv = *reinterpret_cast<const float4*>(&sKR[m * MAT_STRIDE + j0]);
                const float q4[4] = {qv.x, qv.y, qv.z, qv.w};
                const float k4[4] = {kv.x, kv.y, kv.z, kv.w};
                #pragma unroll
                for (int ii = 0; ii < 4; ++ii)
                    #pragma unroll
                    for (int jj = 0; jj < 4; ++jj)
                        acc[ii][jj] += q4[ii] * k4[jj];
            }
            #pragma unroll
            for (int ii = 0; ii < 4; ++ii)
                #pragma unroll
                for (int jj = 0; jj < 4; ++jj) {
                    const int i = i0 + ii, j = j0 + jj;
                    const float v = acc[ii][jj] + sQR[i * MAT_STRIDE + j] + sKR[i * MAT_STRIDE + j];
                    sSim[i * MAT_STRIDE + j] = v * sGS[j] + sBS[j];
                }
        }
        __syncthreads();

        // softmax over j, warp per row (4 warps / sub-block)
        {
            const int lane = t0 & 31, w4 = t0 >> 5;
            for (int r = w4; r < KS; r += 4) {
                float* row = sSim + r * MAT_STRIDE;
                const float v0 = row[lane];
                const float v1 = (lane < 16) ? row[32 + lane] : -3.0e38f;
                float mx = fmaxf(v0, v1);
                #pragma unroll
                for (int off = 16; off > 0; off >>= 1)
                    mx = fmaxf(mx, __shfl_xor_sync(0xffffffffu, mx, off));
                const float e0 = __expf(v0 - mx);
                const float e1 = (lane < 16) ? __expf(v1 - mx) : 0.f;
                float sumv = e0 + e1;
                #pragma unroll
                for (int off = 16; off > 0; off >>= 1)
                    sumv += __shfl_xor_sync(0xffffffffu, sumv, off);
                const float rinv = __fdividef(1.0f, sumv);
                row[lane] = e0 * rinv;
                if (lane < 16) row[32 + lane] = e1 * rinv;
            }
        }
        __syncthreads();

        // out[8g+c, i] = (sum_j sim[i,j]*(v[c,j] + rel[8+c, i-j+47]))*go[i] + 2*bo[i]
        for (int s = t0; s < 8 * KS; s += 128) {
            const int c = s / KS, i = s % KS;
            const float* simrow = sSim + i * MAT_STRIDE;
            const float* vrow = V + c * QKV_STRIDE;
            const float* rrow = sRel + (8 + c) * REL_STRIDE + i + 47;
            float acc = 0.f;
            #pragma unroll 4
            for (int j = 0; j < KS; ++j)
                acc += simrow[j] * (vrow[j] + rrow[-j]);
            sOut[i * OUT_STRIDE + 8 * g + c] = acc * sGO[i] + sBO[i];
        }
        __syncthreads();
    }

    // ---- write out: out[0, i, wi, li, p] ----
    for (int idx = tid; idx < KS * 64; idx += NT) {
        const int i = idx >> 6, p = idx & 63;
        out[((i * KS + wi) * KS + li) * 64 + p] = sOut[i * OUT_STRIDE + p];
    }
}

extern "C" void kernel_launch(void* const* d_in, const int* in_sizes, int n_in,
                              void* d_out, int out_size) {
    (void)in_sizes; (void)n_in; (void)out_size;
    cudaFuncSetAttribute(axial_kernel, cudaFuncAttributeMaxDynamicSharedMemorySize, SMEM_BYTES);
    axial_kernel<<<KS * KS, NT, SMEM_BYTES>>>(
        (const float*)d_in[0], (const float*)d_in[1], (const float*)d_in[2],
        (const float*)d_in[3], (const float*)d_in[4], (const float*)d_in[5],
        (const float*)d_in[6], (const float*)d_in[7], (const float*)d_in[8],
        (float*)d_out);
}

// round 2
// speedup vs baseline: 1.5743x; 1.5743x over previous
#include <cuda_runtime.h>

#define KS 48
#define NT 256

typedef unsigned long long ull;

// shared memory layout (floats)
constexpr int SX_STRIDE  = 50;   // X[c][h], even stride for float2
constexpr int W_STRIDE   = 65;   // W[o][c]
constexpr int QKV_STRIDE = 49;   // QKV[o][h]
constexpr int REL_STRIDE = 97;   // rel[c][d], d in [0,95)
constexpr int MAT_STRIDE = 52;   // qr/kr/sim [48][52]
constexpr int OUT_STRIDE = 65;   // out[i][p]

constexpr int OFF_QKV = 0;                              // 6272
constexpr int OFF_REL = OFF_QKV + 128 * QKV_STRIDE;     // +1552
constexpr int OFF_OUT = OFF_REL + 16 * REL_STRIDE;      // +3120
constexpr int OFF_PAR = OFF_OUT + 48 * OUT_STRIDE;      // +288
constexpr int OFF_SCR = OFF_PAR + 6 * 48;               // scratch union
// phase 1: X (64*50=3200) + W (128*65=8320) = 11520
constexpr int OFF_X   = OFF_SCR;
constexpr int OFF_W   = OFF_X + 64 * SX_STRIDE;
// phase 2: QR/KR/SIM, 2 sub-blocks each: 3*2*2496 = 14976
constexpr int OFF_QR  = OFF_SCR;
constexpr int OFF_KR  = OFF_QR + 2 * 48 * MAT_STRIDE;
constexpr int OFF_SIM = OFF_KR + 2 * 48 * MAT_STRIDE;
constexpr int SCR_FLOATS = 3 * 2 * 48 * MAT_STRIDE;     // 14976 > 11520
constexpr int SMEM_FLOATS = OFF_SCR + SCR_FLOATS;       // 26208
constexpr int SMEM_BYTES  = SMEM_FLOATS * 4;            // 104832 B -> 2 CTAs/SM

__device__ __forceinline__ ull dupf(float v) {
    ull r; unsigned u = __float_as_uint(v);
    asm("mov.b64 %0, {%1, %1};" : "=l"(r) : "r"(u));
    return r;
}
__device__ __forceinline__ void ffma2(ull& d, ull a, ull b) {
    asm("fma.rn.f32x2 %0, %1, %2, %0;" : "+l"(d) : "l"(a), "l"(b));
}
__device__ __forceinline__ float f2lo(ull v) { return __uint_as_float((unsigned)(v & 0xffffffffull)); }
__device__ __forceinline__ float f2hi(ull v) { return __uint_as_float((unsigned)(v >> 32)); }

__global__ void __launch_bounds__(NT, 2) axial_kernel(
    const float* __restrict__ x,      const float* __restrict__ w_qkv,
    const float* __restrict__ relv,
    const float* __restrict__ g_qkv,  const float* __restrict__ b_qkv,
    const float* __restrict__ g_sim,  const float* __restrict__ b_sim,
    const float* __restrict__ g_out,  const float* __restrict__ b_out,
    float* __restrict__ out)
{
    extern __shared__ float sm[];
    float* sX   = sm + OFF_X;
    float* sW   = sm + OFF_W;
    float* sQKV = sm + OFF_QKV;
    float* sRel = sm + OFF_REL;
    float* sOut = sm + OFF_OUT;
    float* sGQ  = sm + OFF_PAR;
    float* sBQ  = sGQ + 48; float* sGS = sBQ + 48; float* sBS = sGS + 48;
    float* sGO  = sBS + 48; float* sBO = sGO + 48;

    const int tid = threadIdx.x;
    const int blk = blockIdx.x;
    const int wi = blk / KS, li = blk % KS;

    // ---- load X (as [c][h]), W (stride 65), relative, BN params ----
    for (int idx = tid; idx < KS * 64; idx += NT) {
        const int h = idx >> 6, c = idx & 63;
        sX[c * SX_STRIDE + h] = x[((h * KS + wi) * KS + li) * 64 + c];
    }
    for (int idx = tid; idx < 128 * 64; idx += NT)
        sW[(idx >> 6) * W_STRIDE + (idx & 63)] = w_qkv[idx];
    for (int idx = tid; idx < 16 * 95; idx += NT)
        sRel[(idx / 95) * REL_STRIDE + (idx % 95)] = relv[idx];
    if (tid < KS) {
        const float inv = rsqrtf(1.001f);
        sGQ[tid] = g_qkv[tid] * inv; sBQ[tid] = b_qkv[tid];
        sGS[tid] = g_sim[tid] * inv; sBS[tid] = 3.0f * b_sim[tid];
        sGO[tid] = g_out[tid] * inv; sBO[tid] = 2.0f * b_out[tid];
    }
    __syncthreads();

    // ---- QKV = BN(W @ X): 128x48, exact 4o x 6h tiles (256 tiles) ----
    {
        const int o0 = (tid >> 3) * 4;
        const int h0 = (tid & 7) * 6;
        ull a[4][3];
        #pragma unroll
        for (int q = 0; q < 4; ++q)
            #pragma unroll
            for (int p = 0; p < 3; ++p) a[q][p] = 0ull;
        const float* xrow = sX + h0;
        #pragma unroll 4
        for (int c = 0; c < 64; ++c) {
            const ull* xp = reinterpret_cast<const ull*>(xrow + c * SX_STRIDE);
            const ull x01 = xp[0], x23 = xp[1], x45 = xp[2];
            #pragma unroll
            for (int q = 0; q < 4; ++q) {
                const ull wd = dupf(sW[(o0 + q) * W_STRIDE + c]);
                ffma2(a[q][0], wd, x01);
                ffma2(a[q][1], wd, x23);
                ffma2(a[q][2], wd, x45);
            }
        }
        float gg[6], bb[6];
        #pragma unroll
        for (int p = 0; p < 6; ++p) { gg[p] = sGQ[h0 + p]; bb[p] = sBQ[h0 + p]; }
        #pragma unroll
        for (int q = 0; q < 4; ++q) {
            float* dst = sQKV + (o0 + q) * QKV_STRIDE + h0;
            #pragma unroll
            for (int p = 0; p < 3; ++p) {
                dst[2 * p]     = f2lo(a[q][p]) * gg[2 * p]     + bb[2 * p];
                dst[2 * p + 1] = f2hi(a[q][p]) * gg[2 * p + 1] + bb[2 * p + 1];
            }
        }
    }
    __syncthreads();

    // ---- per-group pipeline; two groups in parallel (128 threads each) ----
    const int sub = tid >> 7;      // 0 or 1
    const int t0  = tid & 127;
    float* sQR  = sm + OFF_QR  + sub * (48 * MAT_STRIDE);
    float* sKR  = sm + OFF_KR  + sub * (48 * MAT_STRIDE);
    float* sSim = sm + OFF_SIM + sub * (48 * MAT_STRIDE);

    for (int gp = 0; gp < 8; gp += 2) {
        const int g = gp + sub;
        const float* Q  = sQKV + (16 * g)     * QKV_STRIDE;
        const float* Km = sQKV + (16 * g + 4) * QKV_STRIDE;
        const float* V  = sQKV + (16 * g + 8) * QKV_STRIDE;

        // qr[m][i] = sum_c q[c,m] * rel[c, m-i+47]
        // kr[m][j] = sum_c k[c,j] * rel[4+c, j-m+47]
        for (int s = t0; s < KS * KS; s += 128) {
            const int m = s / KS, i = s % KS;
            float aq = 0.f, ak = 0.f;
            #pragma unroll
            for (int c = 0; c < 4; ++c) {
                aq += Q[c * QKV_STRIDE + m]  * sRel[c * REL_STRIDE + (m - i + 47)];
                ak += Km[c * QKV_STRIDE + i] * sRel[(4 + c) * REL_STRIDE + (i - m + 47)];
            }
            sQR[m * MAT_STRIDE + i] = aq;
            sKR[m * MAT_STRIDE + i] = ak;
        }
        __syncthreads();

        // qk[i,j] = sum_m qr[m,i]*kr[m,j]  (f32x2 packed over i-pairs)
        for (int ts = t0; ts < 144; ts += 128) {
            const int i0 = (ts / 12) * 4, j0 = (ts % 12) * 4;
            ull acc[2][4];
            #pragma unroll
            for (int p = 0; p < 2; ++p)
                #pragma unroll
                for (int jj = 0; jj < 4; ++jj) acc[p][jj] = 0ull;
            #pragma unroll 4
            for (int m = 0; m < KS; ++m) {
                const ulonglong2 qv = *reinterpret_cast<const ulonglong2*>(&sQR[m * MAT_STRIDE + i0]);
                const float4 kv = *reinterpret_cast<const float4*>(&sKR[m * MAT_STRIDE + j0]);
                const ull k0 = dupf(kv.x), k1 = dupf(kv.y), k2 = dupf(kv.z), k3 = dupf(kv.w);
                ffma2(acc[0][0], qv.x, k0); ffma2(acc[0][1], qv.x, k1);
                ffma2(acc[0][2], qv.x, k2); ffma2(acc[0][3], qv.x, k3);
                ffma2(acc[1][0], qv.y, k0); ffma2(acc[1][1], qv.y, k1);
                ffma2(acc[1][2], qv.y, k2); ffma2(acc[1][3], qv.y, k3);
            }
            #pragma unroll
            for (int p = 0; p < 2; ++p)
                #pragma unroll
                for (int jj = 0; jj < 4; ++jj) {
                    const int j = j0 + jj;
                    const int ia = i0 + 2 * p, ib = ia + 1;
                    const float va = f2lo(acc[p][jj]) + sQR[ia * MAT_STRIDE + j] + sKR[ia * MAT_STRIDE + j];
                    const float vb = f2hi(acc[p][jj]) + sQR[ib * MAT_STRIDE + j] + sKR[ib * MAT_STRIDE + j];
                    sSim[ia * MAT_STRIDE + j] = va * sGS[j] + sBS[j];
                    sSim[ib * MAT_STRIDE + j] = vb * sGS[j] + sBS[j];
                }
        }
        __syncthreads();

        // softmax over j, warp per row
        {
            const int lane = t0 & 31, w4 = t0 >> 5;
            for (int r = w4; r < KS; r += 4) {
                float* row = sSim + r * MAT_STRIDE;
                const float v0 = row[lane];
                const float v1 = (lane < 16) ? row[32 + lane] : -3.0e38f;
                float mx = fmaxf(v0, v1);
                #pragma unroll
                for (int off = 16; off > 0; off >>= 1)
                    mx = fmaxf(mx, __shfl_xor_sync(0xffffffffu, mx, off));
                const float e0 = __expf(v0 - mx);
                const float e1 = (lane < 16) ? __expf(v1 - mx) : 0.f;
                float sumv = e0 + e1;
                #pragma unroll
                for (int off = 16; off > 0; off >>= 1)
                    sumv += __shfl_xor_sync(0xffffffffu, sumv, off);
                const float rinv = __fdividef(1.0f, sumv);
                row[lane] = e0 * rinv;
                if (lane < 16) row[32 + lane] = e1 * rinv;
            }
        }
        __syncthreads();

        // out[8g+c, i] = (sum_j sim[i,j]*(v[c,j] + rel[8+c, i-j+47]))*go[i] + 2*bo[i]
        // 2c x 2i tiles: 96 tiles over 128 threads
        if (t0 < 96) {
            const int c0 = (t0 / 24) * 2;
            const int i0 = (t0 % 24) * 2;
            const float* s0r = sSim + i0 * MAT_STRIDE;
            const float* s1r = s0r + MAT_STRIDE;
            const float* v0r = V + c0 * QKV_STRIDE;
            const float* v1r = v0r + QKV_STRIDE;
            const float* r0r = sRel + (8 + c0) * REL_STRIDE + i0 + 47;
            const float* r1r = r0r + REL_STRIDE;
            float a00 = 0.f, a01 = 0.f, a10 = 0.f, a11 = 0.f;
            #pragma unroll 4
            for (int j = 0; j < KS; ++j) {
                const float s0 = s0r[j], s1 = s1r[j];
                const float v0 = v0r[j], v1 = v1r[j];
                const float ra = r0r[-j], rb = r0r[1 - j];
                const float rc = r1r[-j], rd = r1r[1 - j];
                a00 += s0 * (v0 + ra); a01 += s1 * (v0 + rb);
                a10 += s0 * (v1 + rc); a11 += s1 * (v1 + rd);
            }
            const float g0 = sGO[i0], g1 = sGO[i0 + 1];
            const float b0 = sBO[i0], b1 = sBO[i0 + 1];
            sOut[i0 * OUT_STRIDE + 8 * g + c0]           = a00 * g0 + b0;
            sOut[(i0 + 1) * OUT_STRIDE + 8 * g + c0]     = a01 * g1 + b1;
            sOut[i0 * OUT_STRIDE + 8 * g + c0 + 1]       = a10 * g0 + b0;
            sOut[(i0 + 1) * OUT_STRIDE + 8 * g + c0 + 1] = a11 * g1 + b1;
        }
        __syncthreads();
    }

    // ---- write out: out[0, i, wi, li, p] ----
    for (int idx = tid; idx < KS * 64; idx += NT) {
        const int i = idx >> 6, p = idx & 63;
        out[((i * KS + wi) * KS + li) * 64 + p] = sOut[i * OUT_STRIDE + p];
    }
}

extern "C" void kernel_launch(void* const* d_in, const int* in_sizes, int n_in,
                              void* d_out, int out_size) {
    (void)in_sizes; (void)n_in; (void)out_size;
    cudaFuncSetAttribute(axial_kernel, cudaFuncAttributeMaxDynamicSharedMemorySize, SMEM_BYTES);
    axial_kernel<<<KS * KS, NT, SMEM_BYTES>>>(
        (const float*)d_in[0], (const float*)d_in[1], (const float*)d_in[2],
        (const float*)d_in[3], (const float*)d_in[4], (const float*)d_in[5],
        (const float*)d_in[6], (const float*)d_in[7], (const float*)d_in[8],
        (float*)d_out);
}

// round 4
// speedup vs baseline: 1.8058x; 1.1470x over previous
#include <cuda_runtime.h>

#define KS 48
#define NT 256

typedef unsigned long long ull;

// strides (floats)
constexpr int SX_STRIDE  = 50;   // X[c][h]
constexpr int W_STRIDE   = 65;   // W[o][c]
constexpr int QKV_STRIDE = 49;   // QKV[o][h]
constexpr int REL_STRIDE = 97;   // rel[c][d]
constexpr int QK_STRIDE  = 50;   // QR/KR [48][50]
constexpr int SIM_STRIDE = 51;   // SIM   [48][51]
constexpr int OUT_STRIDE = 65;   // out[i][p]

constexpr int OFF_QKV = 0;                              // 6272
constexpr int OFF_REL = OFF_QKV + 128 * QKV_STRIDE;     // +1552
constexpr int OFF_OUT = OFF_REL + 16 * REL_STRIDE;      // +3120
constexpr int OFF_PAR = OFF_OUT + 48 * OUT_STRIDE;      // +288
constexpr int OFF_SCR = OFF_PAR + 6 * 48;
// phase 1 scratch: X (64*50) + W (128*65) = 11520
constexpr int OFF_X   = OFF_SCR;
constexpr int OFF_W   = OFF_X + 64 * SX_STRIDE;
// phase 2 scratch: QR/KR (2 groups each) + SIM (2 groups) = 14496
constexpr int OFF_QR  = OFF_SCR;
constexpr int OFF_KR  = OFF_QR + 2 * 48 * QK_STRIDE;
constexpr int OFF_SIM = OFF_KR + 2 * 48 * QK_STRIDE;
constexpr int SCR_FLOATS  = 4 * 48 * QK_STRIDE + 2 * 48 * SIM_STRIDE;  // 14496
constexpr int SMEM_FLOATS = OFF_SCR + SCR_FLOATS;        // 25728
constexpr int SMEM_BYTES  = SMEM_FLOATS * 4;             // 102912 -> 2 CTAs/SM

__device__ __forceinline__ ull dupf(float v) {
    ull r; unsigned u = __float_as_uint(v);
    asm("mov.b64 %0, {%1, %1};" : "=l"(r) : "r"(u));
    return r;
}
__device__ __forceinline__ void ffma2(ull& d, ull a, ull b) {
    asm("fma.rn.f32x2 %0, %1, %2, %0;" : "+l"(d) : "l"(a), "l"(b));
}
__device__ __forceinline__ float f2lo(ull v) { return __uint_as_float((unsigned)(v & 0xffffffffull)); }
__device__ __forceinline__ float f2hi(ull v) { return __uint_as_float((unsigned)(v >> 32)); }

__global__ void __launch_bounds__(NT, 2) axial_kernel(
    const float* __restrict__ x,      const float* __restrict__ w_qkv,
    const float* __restrict__ relv,
    const float* __restrict__ g_qkv,  const float* __restrict__ b_qkv,
    const float* __restrict__ g_sim,  const float* __restrict__ b_sim,
    const float* __restrict__ g_out,  const float* __restrict__ b_out,
    float* __restrict__ out)
{
    extern __shared__ float sm[];
    float* sX   = sm + OFF_X;
    float* sW   = sm + OFF_W;
    float* sQKV = sm + OFF_QKV;
    float* sRel = sm + OFF_REL;
    float* sOut = sm + OFF_OUT;
    float* sGQ  = sm + OFF_PAR;
    float* sBQ  = sGQ + 48; float* sGS = sBQ + 48; float* sBS = sGS + 48;
    float* sGO  = sBS + 48; float* sBO = sGO + 48;

    const int tid = threadIdx.x;
    const int blk = blockIdx.x;
    const int wi = blk / KS, li = blk % KS;

    // ---- load X (as [c][h]), W, relative, BN params ----
    for (int idx = tid; idx < KS * 64; idx += NT) {
        const int h = idx >> 6, c = idx & 63;
        sX[c * SX_STRIDE + h] = x[((h * KS + wi) * KS + li) * 64 + c];
    }
    for (int idx = tid; idx < 128 * 64; idx += NT)
        sW[(idx >> 6) * W_STRIDE + (idx & 63)] = w_qkv[idx];
    for (int idx = tid; idx < 16 * 95; idx += NT)
        sRel[(idx / 95) * REL_STRIDE + (idx % 95)] = relv[idx];
    if (tid < KS) {
        const float inv = rsqrtf(1.001f);
        sGQ[tid] = g_qkv[tid] * inv; sBQ[tid] = b_qkv[tid];
        sGS[tid] = g_sim[tid] * inv; sBS[tid] = 3.0f * b_sim[tid];
        sGO[tid] = g_out[tid] * inv; sBO[tid] = 2.0f * b_out[tid];
    }
    __syncthreads();

    // ---- QKV = BN(W @ X): 128x48, exact 4o x 6h tiles (256 tiles) ----
    {
        const int o0 = (tid >> 3) * 4;
        const int h0 = (tid & 7) * 6;
        ull a[4][3];
        #pragma unroll
        for (int q = 0; q < 4; ++q)
            #pragma unroll
            for (int p = 0; p < 3; ++p) a[q][p] = 0ull;
        const float* xrow = sX + h0;
        #pragma unroll 4
        for (int c = 0; c < 64; ++c) {
            const ull* xp = reinterpret_cast<const ull*>(xrow + c * SX_STRIDE);
            const ull x01 = xp[0], x23 = xp[1], x45 = xp[2];
            #pragma unroll
            for (int q = 0; q < 4; ++q) {
                const ull wd = dupf(sW[(o0 + q) * W_STRIDE + c]);
                ffma2(a[q][0], wd, x01);
                ffma2(a[q][1], wd, x23);
                ffma2(a[q][2], wd, x45);
            }
        }
        float gg[6], bb[6];
        #pragma unroll
        for (int p = 0; p < 6; ++p) { gg[p] = sGQ[h0 + p]; bb[p] = sBQ[h0 + p]; }
        #pragma unroll
        for (int q = 0; q < 4; ++q) {
            float* dst = sQKV + (o0 + q) * QKV_STRIDE + h0;
            #pragma unroll
            for (int p = 0; p < 3; ++p) {
                dst[2 * p]     = f2lo(a[q][p]) * gg[2 * p]     + bb[2 * p];
                dst[2 * p + 1] = f2hi(a[q][p]) * gg[2 * p + 1] + bb[2 * p + 1];
            }
        }
    }
    __syncthreads();

    // ---- 4 passes, 2 groups each; all 256 threads cooperate on both ----
    for (int gp = 0; gp < 8; gp += 2) {

        // == qr/kr: 2304 quad-tasks (qr tiles i, kr tiles m), 9 per thread ==
        for (int q = tid; q < 2304; q += NT) {
            if (q < 1152) {
                const int grp = q / 576; const int r = q - grp * 576;
                const int m = r / 12, i0 = (r % 12) * 4;
                const float* Q = sQKV + (16 * (gp + grp)) * QKV_STRIDE;
                float* QRg = sm + OFF_QR + grp * (48 * QK_STRIDE);
                float a0 = 0.f, a1 = 0.f, a2 = 0.f, a3 = 0.f;
                #pragma unroll
                for (int c = 0; c < 4; ++c) {
                    const float qc = Q[c * QKV_STRIDE + m];
                    const float* rl = sRel + c * REL_STRIDE + (m - i0 + 47);
                    a0 += qc * rl[0]; a1 += qc * rl[-1];
                    a2 += qc * rl[-2]; a3 += qc * rl[-3];
                }
                float* d = QRg + m * QK_STRIDE + i0;
                d[0] = a0; d[1] = a1; d[2] = a2; d[3] = a3;
            } else {
                int r = q - 1152; const int grp = r / 576; r -= grp * 576;
                const int j = r / 12, m0 = (r % 12) * 4;
                const float* Kp = sQKV + (16 * (gp + grp) + 4) * QKV_STRIDE;
                float* KRg = sm + OFF_KR + grp * (48 * QK_STRIDE);
                float a0 = 0.f, a1 = 0.f, a2 = 0.f, a3 = 0.f;
                #pragma unroll
                for (int c = 0; c < 4; ++c) {
                    const float kc = Kp[c * QKV_STRIDE + j];
                    const float* rl = sRel + (4 + c) * REL_STRIDE + (j - m0 + 47);
                    a0 += kc * rl[0]; a1 += kc * rl[-1];
                    a2 += kc * rl[-2]; a3 += kc * rl[-3];
                }
                KRg[m0 * QK_STRIDE + j]       = a0;
                KRg[(m0 + 1) * QK_STRIDE + j] = a1;
                KRg[(m0 + 2) * QK_STRIDE + j] = a2;
                KRg[(m0 + 3) * QK_STRIDE + j] = a3;
            }
        }
        __syncthreads();

        // == qk: 6x6 tiles, m-split over lane pairs, shfl reduce (float halves) ==
        {
            const int mhalf = tid & 1;
            const int tile  = tid >> 1;          // 0..127
            const int grp   = tile >> 6;
            const int tt    = tile & 63;
            const int i0    = (tt & 7) * 6;
            const int j0    = (tt >> 3) * 6;
            const float* QRg = sm + OFF_QR + grp * (48 * QK_STRIDE);
            const float* KRg = sm + OFF_KR + grp * (48 * QK_STRIDE);
            float* SIMg = sm + OFF_SIM + grp * (48 * SIM_STRIDE);

            ull acc[3][6];
            #pragma unroll
            for (int p = 0; p < 3; ++p)
                #pragma unroll
                for (int jj = 0; jj < 6; ++jj) acc[p][jj] = 0ull;

            const int mbase = mhalf * 24;
            #pragma unroll 4
            for (int mm = 0; mm < 24; ++mm) {
                const float* qp = QRg + (mbase + mm) * QK_STRIDE + i0;
                const ull q01 = reinterpret_cast<const ull*>(qp)[0];
                const ull q23 = reinterpret_cast<const ull*>(qp)[1];
                const ull q45 = reinterpret_cast<const ull*>(qp)[2];
                const float* kp = KRg + (mbase + mm) * QK_STRIDE + j0;
                #pragma unroll
                for (int jj = 0; jj < 6; ++jj) {
                    const ull kd = dupf(kp[jj]);
                    ffma2(acc[0][jj], q01, kd);
                    ffma2(acc[1][jj], q23, kd);
                    ffma2(acc[2][jj], q45, kd);
                }
            }
            // combine m-halves across the lane pair: shuffle packed, add as floats
            float full[6][6];   // [row within tile][j]
            #pragma unroll
            for (int p = 0; p < 3; ++p)
                #pragma unroll
                for (int jj = 0; jj < 6; ++jj) {
                    const ull other = __shfl_xor_sync(0xffffffffu, acc[p][jj], 1);
                    full[2 * p][jj]     = f2lo(acc[p][jj]) + f2lo(other);
                    full[2 * p + 1][jj] = f2hi(acc[p][jj]) + f2hi(other);
                }
            // each lane writes 3 rows: mhalf0 -> rows 0..2, mhalf1 -> rows 3..5
            const int rbase = mhalf * 3;
            #pragma unroll
            for (int rr = 0; rr < 3; ++rr) {
                const int i = i0 + rbase + rr;
                const float* qrow = QRg + i * QK_STRIDE + j0;
                const float* krow = KRg + i * QK_STRIDE + j0;
                float* srow = SIMg + i * SIM_STRIDE + j0;
                #pragma unroll
                for (int jj = 0; jj < 6; ++jj) {
                    const int j = j0 + jj;
                    const float v = full[rbase + rr][jj] + qrow[jj] + krow[jj];
                    srow[jj] = v * sGS[j] + sBS[j];
                }
            }
        }
        __syncthreads();

        // == softmax over j; 96 rows over 8 warps (SIM groups are contiguous) ==
        {
            const int lane = tid & 31, wp = tid >> 5;
            for (int r = wp; r < 96; r += 8) {
                float* row = sm + OFF_SIM + r * SIM_STRIDE;
                const float v0 = row[lane];
                const float v1 = (lane < 16) ? row[32 + lane] : -3.0e38f;
                float mx = fmaxf(v0, v1);
                #pragma unroll
                for (int off = 16; off > 0; off >>= 1)
                    mx = fmaxf(mx, __shfl_xor_sync(0xffffffffu, mx, off));
                const float e0 = __expf(v0 - mx);
                const float e1 = (lane < 16) ? __expf(v1 - mx) : 0.f;
                float sumv = e0 + e1;
                #pragma unroll
                for (int off = 16; off > 0; off >>= 1)
                    sumv += __shfl_xor_sync(0xffffffffu, sumv, off);
                const float rinv = __fdividef(1.0f, sumv);
                row[lane] = e0 * rinv;
                if (lane < 16) row[32 + lane] = e1 * rinv;
            }
        }
        __syncthreads();

        // == sv: 4c x 3i tiles x 4 j-splits (256 tasks), shfl reduce ==
        {
            const int jq   = tid & 3;
            const int tile = tid >> 2;           // 0..63
            const int grp  = tile >> 5;
            const int tt   = tile & 31;
            const int c0   = (tt >> 4) * 4;
            const int i0   = (tt & 15) * 3;
            const float* SIMg = sm + OFF_SIM + grp * (48 * SIM_STRIDE);
            const float* V = sQKV + (16 * (gp + grp) + 8) * QKV_STRIDE;

            float acc[4][3];
            #pragma unroll
            for (int cc = 0; cc < 4; ++cc)
                #pragma unroll
                for (int ii = 0; ii < 3; ++ii) acc[cc][ii] = 0.f;

            const int jb = jq * 12;
            #pragma unroll 4
            for (int jj = 0; jj < 12; ++jj) {
                const int j = jb + jj;
                const float s0 = SIMg[i0 * SIM_STRIDE + j];
                const float s1 = SIMg[(i0 + 1) * SIM_STRIDE + j];
                const float s2 = SIMg[(i0 + 2) * SIM_STRIDE + j];
                #pragma unroll
                for (int cc = 0; cc < 4; ++cc) {
                    const float vv = V[(c0 + cc) * QKV_STRIDE + j];
                    const float* rl = sRel + (8 + c0 + cc) * REL_STRIDE + (i0 - j + 47);
                    acc[cc][0] += s0 * (vv + rl[0]);
                    acc[cc][1] += s1 * (vv + rl[1]);
                    acc[cc][2] += s2 * (vv + rl[2]);
                }
            }
            #pragma unroll
            for (int cc = 0; cc < 4; ++cc)
                #pragma unroll
                for (int ii = 0; ii < 3; ++ii) {
                    acc[cc][ii] += __shfl_xor_sync(0xffffffffu, acc[cc][ii], 1);
                    acc[cc][ii] += __shfl_xor_sync(0xffffffffu, acc[cc][ii], 2);
                }
            // lane jq writes channel c0+jq (static select, no local-mem spill)
            const int c = c0 + jq;
            #pragma unroll
            for (int ii = 0; ii < 3; ++ii) {
                const float av = (jq == 0) ? acc[0][ii] :
                                 (jq == 1) ? acc[1][ii] :
                                 (jq == 2) ? acc[2][ii] : acc[3][ii];
                const int i = i0 + ii;
                sOut[i * OUT_STRIDE + 8 * (gp + grp) + c] = av * sGO[i] + sBO[i];
            }
        }
        __syncthreads();
    }

    // ---- write out: out[0, i, wi, li, p] ----
    for (int idx = tid; idx < KS * 64; idx += NT) {
        const int i = idx >> 6, p = idx & 63;
        out[((i * KS + wi) * KS + li) * 64 + p] = sOut[i * OUT_STRIDE + p];
    }
}

extern "C" void kernel_launch(void* const* d_in, const int* in_sizes, int n_in,
                              void* d_out, int out_size) {
    (void)in_sizes; (void)n_in; (void)out_size;
    cudaFuncSetAttribute(axial_kernel, cudaFuncAttributeMaxDynamicSharedMemorySize, SMEM_BYTES);
    axial_kernel<<<KS * KS, NT, SMEM_BYTES>>>(
        (const float*)d_in[0], (const float*)d_in[1], (const float*)d_in[2],
        (const float*)d_in[3], (const float*)d_in[4], (const float*)d_in[5],
        (const float*)d_in[6], (const float*)d_in[7], (const float*)d_in[8],
        (float*)d_out);
}

// round 5
// speedup vs baseline: 1.9623x; 1.0867x over previous
#include <cuda_runtime.h>

#define KS 48
#define NT 256

typedef unsigned long long ull;

// strides (floats)
constexpr int SX_STRIDE  = 50;   // X[c][h]
constexpr int W_STRIDE   = 65;   // W[o][c]
constexpr int QKV_STRIDE = 49;   // QKV[o][h]
constexpr int REL_STRIDE = 97;   // rel[c][d]
constexpr int QK_STRIDE  = 50;   // QR/KR [48][50]  (even: ull loads)
constexpr int SIM_STRIDE = 51;   // SIM   [48][51]
constexpr int OUT_STRIDE = 65;   // out[i][p]

constexpr int QK_G  = 48 * QK_STRIDE + 16;  // 2416: group stride, ≡16 mod 32 (kills qk 2-way conflicts)
constexpr int SIM_G = 48 * SIM_STRIDE;      // 2448: ≡16 mod 32 already

constexpr int OFF_QKV = 0;                              // 6272
constexpr int OFF_REL = OFF_QKV + 128 * QKV_STRIDE;     // +1552
constexpr int OFF_OUT = OFF_REL + 16 * REL_STRIDE;      // +3120
constexpr int OFF_PAR = OFF_OUT + 48 * OUT_STRIDE;      // +288
constexpr int OFF_SCR = OFF_PAR + 6 * 48;               // 11232 (even)
// phase 1 scratch: X (64*50) + W (128*65) = 11520
constexpr int OFF_X   = OFF_SCR;
constexpr int OFF_W   = OFF_X + 64 * SX_STRIDE;
// phase 2 scratch: QR/KR (2 groups, padded) + SIM (2 groups) = 14560
constexpr int OFF_QR  = OFF_SCR;
constexpr int OFF_KR  = OFF_QR + 2 * QK_G;
constexpr int OFF_SIM = OFF_KR + 2 * QK_G;
constexpr int SCR_FLOATS  = 4 * QK_G + 2 * SIM_G;        // 14560 > 11520
constexpr int SMEM_FLOATS = OFF_SCR + SCR_FLOATS;        // 25792
constexpr int SMEM_BYTES  = SMEM_FLOATS * 4;             // 103168 B -> 2 CTAs/SM

__device__ __forceinline__ ull dupf(float v) {
    ull r; unsigned u = __float_as_uint(v);
    asm("mov.b64 %0, {%1, %1};" : "=l"(r) : "r"(u));
    return r;
}
__device__ __forceinline__ void ffma2(ull& d, ull a, ull b) {
    asm("fma.rn.f32x2 %0, %1, %2, %0;" : "+l"(d) : "l"(a), "l"(b));
}
__device__ __forceinline__ float f2lo(ull v) { return __uint_as_float((unsigned)(v & 0xffffffffull)); }
__device__ __forceinline__ float f2hi(ull v) { return __uint_as_float((unsigned)(v >> 32)); }

__global__ void __launch_bounds__(NT, 2) axial_kernel(
    const float* __restrict__ x,      const float* __restrict__ w_qkv,
    const float* __restrict__ relv,
    const float* __restrict__ g_qkv,  const float* __restrict__ b_qkv,
    const float* __restrict__ g_sim,  const float* __restrict__ b_sim,
    const float* __restrict__ g_out,  const float* __restrict__ b_out,
    float* __restrict__ out)
{
    extern __shared__ float sm[];
    float* sX   = sm + OFF_X;
    float* sW   = sm + OFF_W;
    float* sQKV = sm + OFF_QKV;
    float* sRel = sm + OFF_REL;
    float* sOut = sm + OFF_OUT;
    float* sGQ  = sm + OFF_PAR;
    float* sBQ  = sGQ + 48; float* sGS = sBQ + 48; float* sBS = sGS + 48;
    float* sGO  = sBS + 48; float* sBO = sGO + 48;

    const int tid = threadIdx.x;
    const int blk = blockIdx.x;
    const int wi = blk / KS, li = blk % KS;

    // ---- load X (as [c][h]), W, relative, BN params ----
    for (int idx = tid; idx < KS * 64; idx += NT) {
        const int h = idx >> 6, c = idx & 63;
        sX[c * SX_STRIDE + h] = x[((h * KS + wi) * KS + li) * 64 + c];
    }
    for (int idx = tid; idx < 128 * 64; idx += NT)
        sW[(idx >> 6) * W_STRIDE + (idx & 63)] = w_qkv[idx];
    for (int idx = tid; idx < 16 * 95; idx += NT)
        sRel[(idx / 95) * REL_STRIDE + (idx % 95)] = relv[idx];
    if (tid < KS) {
        const float inv = rsqrtf(1.001f);
        sGQ[tid] = g_qkv[tid] * inv; sBQ[tid] = b_qkv[tid];
        sGS[tid] = g_sim[tid] * inv; sBS[tid] = 3.0f * b_sim[tid];
        sGO[tid] = g_out[tid] * inv; sBO[tid] = 2.0f * b_out[tid];
    }
    __syncthreads();

    // ---- QKV = BN(W @ X): 128x48, exact 4o x 6h tiles (256 tiles) ----
    {
        const int o0 = (tid >> 3) * 4;
        const int h0 = (tid & 7) * 6;
        ull a[4][3];
        #pragma unroll
        for (int q = 0; q < 4; ++q)
            #pragma unroll
            for (int p = 0; p < 3; ++p) a[q][p] = 0ull;
        const float* xrow = sX + h0;
        #pragma unroll 4
        for (int c = 0; c < 64; ++c) {
            const ull* xp = reinterpret_cast<const ull*>(xrow + c * SX_STRIDE);
            const ull x01 = xp[0], x23 = xp[1], x45 = xp[2];
            #pragma unroll
            for (int q = 0; q < 4; ++q) {
                const ull wd = dupf(sW[(o0 + q) * W_STRIDE + c]);
                ffma2(a[q][0], wd, x01);
                ffma2(a[q][1], wd, x23);
                ffma2(a[q][2], wd, x45);
            }
        }
        float gg[6], bb[6];
        #pragma unroll
        for (int p = 0; p < 6; ++p) { gg[p] = sGQ[h0 + p]; bb[p] = sBQ[h0 + p]; }
        #pragma unroll
        for (int q = 0; q < 4; ++q) {
            float* dst = sQKV + (o0 + q) * QKV_STRIDE + h0;
            #pragma unroll
            for (int p = 0; p < 3; ++p) {
                dst[2 * p]     = f2lo(a[q][p]) * gg[2 * p]     + bb[2 * p];
                dst[2 * p + 1] = f2hi(a[q][p]) * gg[2 * p + 1] + bb[2 * p + 1];
            }
        }
    }
    __syncthreads();

    // ---- 4 passes, 2 groups each; all 256 threads cooperate on both ----
    for (int gp = 0; gp < 8; gp += 2) {

        // == qr/kr: 2304 quad-tasks, i (resp. m) strided by 12 -> rel loads are
        //    14 consecutive warp addresses = conflict-free ==
        for (int q = tid; q < 2304; q += NT) {
            if (q < 1152) {
                const int grp = q / 576; const int r = q - grp * 576;
                const int m = r / 12, il = r % 12;
                const float* Q = sQKV + (16 * (gp + grp)) * QKV_STRIDE;
                float* QRg = sm + OFF_QR + grp * QK_G;
                float a0 = 0.f, a1 = 0.f, a2 = 0.f, a3 = 0.f;
                #pragma unroll
                for (int c = 0; c < 4; ++c) {
                    const float qc = Q[c * QKV_STRIDE + m];
                    const float* rl = sRel + c * REL_STRIDE + (m - il + 47);
                    a0 += qc * rl[0];   a1 += qc * rl[-12];
                    a2 += qc * rl[-24]; a3 += qc * rl[-36];
                }
                float* d = QRg + m * QK_STRIDE + il;
                d[0] = a0; d[12] = a1; d[24] = a2; d[36] = a3;
            } else {
                int r = q - 1152; const int grp = r / 576; r -= grp * 576;
                const int j = r / 12, ml = r % 12;
                const float* Kp = sQKV + (16 * (gp + grp) + 4) * QKV_STRIDE;
                float* KRg = sm + OFF_KR + grp * QK_G;
                float a0 = 0.f, a1 = 0.f, a2 = 0.f, a3 = 0.f;
                #pragma unroll
                for (int c = 0; c < 4; ++c) {
                    const float kc = Kp[c * QKV_STRIDE + j];
                    const float* rl = sRel + (4 + c) * REL_STRIDE + (j - ml + 47);
                    a0 += kc * rl[0];   a1 += kc * rl[-12];
                    a2 += kc * rl[-24]; a3 += kc * rl[-36];
                }
                KRg[ml * QK_STRIDE + j]        = a0;
                KRg[(ml + 12) * QK_STRIDE + j] = a1;
                KRg[(ml + 24) * QK_STRIDE + j] = a2;
                KRg[(ml + 36) * QK_STRIDE + j] = a3;
            }
        }
        __syncthreads();

        // == qk: 6x6 tiles, m-split over lane pairs, shfl reduce (float halves) ==
        {
            const int mhalf = tid & 1;
            const int tile  = tid >> 1;          // 0..127
            const int grp   = tile >> 6;
            const int tt    = tile & 63;
            const int i0    = (tt & 7) * 6;
            const int j0    = (tt >> 3) * 6;
            const float* QRg = sm + OFF_QR + grp * QK_G;
            const float* KRg = sm + OFF_KR + grp * QK_G;
            float* SIMg = sm + OFF_SIM + grp * SIM_G;

            ull acc[3][6];
            #pragma unroll
            for (int p = 0; p < 3; ++p)
                #pragma unroll
                for (int jj = 0; jj < 6; ++jj) acc[p][jj] = 0ull;

            const int mbase = mhalf * 24;
            #pragma unroll 4
            for (int mm = 0; mm < 24; ++mm) {
                const float* qp = QRg + (mbase + mm) * QK_STRIDE + i0;
                const ull q01 = reinterpret_cast<const ull*>(qp)[0];
                const ull q23 = reinterpret_cast<const ull*>(qp)[1];
                const ull q45 = reinterpret_cast<const ull*>(qp)[2];
                const float* kp = KRg + (mbase + mm) * QK_STRIDE + j0;
                #pragma unroll
                for (int jj = 0; jj < 6; ++jj) {
                    const ull kd = dupf(kp[jj]);
                    ffma2(acc[0][jj], q01, kd);
                    ffma2(acc[1][jj], q23, kd);
                    ffma2(acc[2][jj], q45, kd);
                }
            }
            // combine m-halves across the lane pair: shuffle packed, add as floats
            float full[6][6];   // [row within tile][j]
            #pragma unroll
            for (int p = 0; p < 3; ++p)
                #pragma unroll
                for (int jj = 0; jj < 6; ++jj) {
                    const ull other = __shfl_xor_sync(0xffffffffu, acc[p][jj], 1);
                    full[2 * p][jj]     = f2lo(acc[p][jj]) + f2lo(other);
                    full[2 * p + 1][jj] = f2hi(acc[p][jj]) + f2hi(other);
                }
            // each lane writes 3 rows: mhalf0 -> rows 0..2, mhalf1 -> rows 3..5
            const int rbase = mhalf * 3;
            #pragma unroll
            for (int rr = 0; rr < 3; ++rr) {
                const int i = i0 + rbase + rr;
                const float* qrow = QRg + i * QK_STRIDE + j0;
                const float* krow = KRg + i * QK_STRIDE + j0;
                float* srow = SIMg + i * SIM_STRIDE + j0;
                #pragma unroll
                for (int jj = 0; jj < 6; ++jj) {
                    const int j = j0 + jj;
                    const float v = full[rbase + rr][jj] + qrow[jj] + krow[jj];
                    srow[jj] = v * sGS[j] + sBS[j];
                }
            }
        }
        __syncthreads();

        // == softmax over j; 96 rows over 8 warps (SIM groups contiguous) ==
        {
            const int lane = tid & 31, wp = tid >> 5;
            for (int r = wp; r < 96; r += 8) {
                float* row = sm + OFF_SIM + r * SIM_STRIDE;
                const float v0 = row[lane];
                const float v1 = (lane < 16) ? row[32 + lane] : -3.0e38f;
                float mx = fmaxf(v0, v1);
                #pragma unroll
                for (int off = 16; off > 0; off >>= 1)
                    mx = fmaxf(mx, __shfl_xor_sync(0xffffffffu, mx, off));
                const float e0 = __expf(v0 - mx);
                const float e1 = (lane < 16) ? __expf(v1 - mx) : 0.f;
                float sumv = e0 + e1;
                #pragma unroll
                for (int off = 16; off > 0; off >>= 1)
                    sumv += __shfl_xor_sync(0xffffffffu, sumv, off);
                const float rinv = __fdividef(1.0f, sumv);
                row[lane] = e0 * rinv;
                if (lane < 16) row[32 + lane] = e1 * rinv;
            }
        }
        __syncthreads();

        // == sv: 4c x 3i tiles x 4 j-splits; rel windows preloaded (CSE), shfl reduce ==
        {
            const int jq   = tid & 3;
            const int tile = tid >> 2;           // 0..63
            const int grp  = tile >> 5;
            const int tt   = tile & 31;
            const int c0   = (tt >> 4) * 4;
            const int i0   = (tt & 15) * 3;
            const float* SIMg = sm + OFF_SIM + grp * SIM_G;
            const float* V = sQKV + (16 * (gp + grp) + 8) * QKV_STRIDE;
            const int jb = jq * 12;

            // rel window: rel idx for (jj, ii) = i0 + ii - (jb+jj) + 47 = base + (11 - jj + ii)
            float w[4][14];
            #pragma unroll
            for (int cc = 0; cc < 4; ++cc) {
                const float* base = sRel + (8 + c0 + cc) * REL_STRIDE + (i0 - jb + 36);
                #pragma unroll
                for (int t = 0; t < 14; ++t) w[cc][t] = base[t];
            }

            float acc[4][3];
            #pragma unroll
            for (int cc = 0; cc < 4; ++cc)
                #pragma unroll
                for (int ii = 0; ii < 3; ++ii) acc[cc][ii] = 0.f;

            #pragma unroll
            for (int jj = 0; jj < 12; ++jj) {
                const int j = jb + jj;
                const float s0 = SIMg[i0 * SIM_STRIDE + j];
                const float s1 = SIMg[(i0 + 1) * SIM_STRIDE + j];
                const float s2 = SIMg[(i0 + 2) * SIM_STRIDE + j];
                #pragma unroll
                for (int cc = 0; cc < 4; ++cc) {
                    const float vv = V[(c0 + cc) * QKV_STRIDE + j];
                    acc[cc][0] += s0 * (vv + w[cc][11 - jj]);
                    acc[cc][1] += s1 * (vv + w[cc][12 - jj]);
                    acc[cc][2] += s2 * (vv + w[cc][13 - jj]);
                }
            }
            #pragma unroll
            for (int cc = 0; cc < 4; ++cc)
                #pragma unroll
                for (int ii = 0; ii < 3; ++ii) {
                    acc[cc][ii] += __shfl_xor_sync(0xffffffffu, acc[cc][ii], 1);
                    acc[cc][ii] += __shfl_xor_sync(0xffffffffu, acc[cc][ii], 2);
                }
            // lane jq writes channel c0+jq (static select, no local-mem spill)
            const int c = c0 + jq;
            #pragma unroll
            for (int ii = 0; ii < 3; ++ii) {
                const float av = (jq == 0) ? acc[0][ii] :
                                 (jq == 1) ? acc[1][ii] :
                                 (jq == 2) ? acc[2][ii] : acc[3][ii];
                const int i = i0 + ii;
                sOut[i * OUT_STRIDE + 8 * (gp + grp) + c] = av * sGO[i] + sBO[i];
            }
        }
        __syncthreads();
    }

    // ---- write out: out[0, i, wi, li, p] ----
    for (int idx = tid; idx < KS * 64; idx += NT) {
        const int i = idx >> 6, p = idx & 63;
        out[((i * KS + wi) * KS + li) * 64 + p] = sOut[i * OUT_STRIDE + p];
    }
}

extern "C" void kernel_launch(void* const* d_in, const int* in_sizes, int n_in,
                              void* d_out, int out_size) {
    (void)in_sizes; (void)n_in; (void)out_size;
    cudaFuncSetAttribute(axial_kernel, cudaFuncAttributeMaxDynamicSharedMemorySize, SMEM_BYTES);
    axial_kernel<<<KS * KS, NT, SMEM_BYTES>>>(
        (const float*)d_in[0], (const float*)d_in[1], (const float*)d_in[2],
        (const float*)d_in[3], (const float*)d_in[4], (const float*)d_in[5],
        (const float*)d_in[6], (const float*)d_in[7], (const float*)d_in[8],
        (float*)d_out);
}